// round 13
// baseline (speedup 1.0000x reference)
#include <cuda_runtime.h>
#include <cuda_fp16.h>
#include <math.h>

#define NMAX 50000
#define EMAX 800000
#define NB1 148                  // build blocks (1/SM, co-resident)
#define BT1 1024
#define NT1 (NB1 * BT1)
#define NB2 592                  // gather blocks (4/SM via launch_bounds)

typedef unsigned long long ull;

// ---------------- scratch (static device memory) ----------------
__device__ float  g_dinv[NMAX];
__device__ int    g_deg[NMAX];            // zeroed by k_gather (prev replay / static init)
__device__ int    g_off[NMAX + 1];
__device__ int    g_cur[NMAX];
__device__ int    g_bsum[NB1 + 8];
__device__ __align__(16) int2 g_csr[EMAX];   // .x = src, .y = weight bits
__device__ __half g_h1[(size_t)NMAX * 128];  // x @ W1 (fp16)
__device__ float  g_h2[(size_t)NMAX * 16];   // relu(agg1+b1) @ W2

// ---------------- software grid barrier (nanosleep backoff, self-restoring) ----------------
__device__ unsigned g_cnt[2] = {0, 0};
__device__ volatile unsigned g_gen[2] = {0, 0};

__device__ __forceinline__ void gbar(int which, unsigned nb) {
    __syncthreads();
    if (threadIdx.x == 0) {
        __threadfence();
        unsigned g = g_gen[which];
        if (atomicAdd(&g_cnt[which], 1u) == nb - 1u) {
            g_cnt[which] = 0u;
            __threadfence();
            g_gen[which] = g + 1u;
        } else {
            while (g_gen[which] == g) __nanosleep(64);
        }
    }
    __syncthreads();
}

// ---------------- f32x2 packed math helpers ----------------
__device__ __forceinline__ ull pk2(float a, float b) {
    ull r;
    asm("mov.b64 %0, {%1, %2};" : "=l"(r) : "f"(a), "f"(b));
    return r;
}
__device__ __forceinline__ float2 up2(ull v) {
    float2 r;
    asm("mov.b64 {%0, %1}, %2;" : "=f"(r.x), "=f"(r.y) : "l"(v));
    return r;
}
__device__ __forceinline__ ull ffma2(ull a, ull b, ull c) {
    ull d;
    asm("fma.rn.f32x2 %0, %1, %2, %3;" : "=l"(d) : "l"(a), "l"(b), "l"(c));
    return d;
}

// ==================== fused CSR build (4 phases; zeroing done by k_gather) ====================
__global__ __launch_bounds__(BT1) void k_build(const int* __restrict__ ei, int n, int E) {
    __shared__ int wsum[32];
    __shared__ int s_carry;
    int tid = threadIdx.x, lane = tid & 31, wid = tid >> 5;
    int b = blockIdx.x;
    int gtid = b * BT1 + tid;

    // ---- P1: dtype detect (block-local) + in-degree count ----
    // int64 little-endian: odd words = zero high halves; int32: random node ids.
    int is64;
    {
        int v = ei[2 * gtid + 1];                 // gtid < NT1 <= 2E, in-bounds both dtypes
        is64 = __syncthreads_or(v != 0) ? 0 : 1;
    }
    if (is64) {
        for (int e = gtid; e < E; e += NT1) atomicAdd(&g_deg[ei[2 * E + 2 * e]], 1);
    } else {
        for (int e = gtid; e < E; e += NT1) atomicAdd(&g_deg[ei[E + e]], 1);
    }
    gbar(0, NB1);

    // ---- P2: per-block local exclusive scan over contiguous region (+ dinv) ----
    int chunk = (n + NB1 - 1) / NB1;
    int r0 = b * chunk;
    int r1 = min(r0 + chunk, n);
    if (tid == 0) s_carry = 0;
    __syncthreads();
    for (int t0 = r0; t0 < r1; t0 += BT1) {
        int i = t0 + tid;
        int deg = (i < r1) ? __ldcg(&g_deg[i]) : 0;
        int v = deg;
#pragma unroll
        for (int o = 1; o < 32; o <<= 1) {
            int t = __shfl_up_sync(0xffffffffu, v, o);
            if (lane >= o) v += t;
        }
        if (lane == 31) wsum[wid] = v;
        __syncthreads();
        if (wid == 0) {
            int s = wsum[lane];
#pragma unroll
            for (int o = 1; o < 32; o <<= 1) {
                int t = __shfl_up_sync(0xffffffffu, s, o);
                if (lane >= o) s += t;
            }
            wsum[lane] = s;
        }
        __syncthreads();
        int excl = s_carry + (wid ? wsum[wid - 1] : 0) + v - deg;
        if (i < r1) {
            g_off[i] = excl;                       // region-local
            g_dinv[i] = rsqrtf((float)deg + 1.0f);
        }
        __syncthreads();
        if (tid == 0) s_carry += wsum[31];
        __syncthreads();
    }
    if (tid == 0) g_bsum[b] = s_carry;
    gbar(0, NB1);

    // ---- P3: block 0 exclusive-scans the NB1 region totals (parallel) ----
    if (b == 0) {
        int v = (tid < NB1) ? __ldcg(&g_bsum[tid]) : 0;
        int x = v;
#pragma unroll
        for (int o = 1; o < 32; o <<= 1) {
            int t = __shfl_up_sync(0xffffffffu, x, o);
            if (lane >= o) x += t;
        }
        if (lane == 31) wsum[wid] = x;
        __syncthreads();
        if (wid == 0) {
            int s = wsum[lane];
#pragma unroll
            for (int o = 1; o < 32; o <<= 1) {
                int t = __shfl_up_sync(0xffffffffu, s, o);
                if (lane >= o) s += t;
            }
            wsum[lane] = s;
        }
        __syncthreads();
        if (tid < NB1) g_bsum[tid] = (wid ? wsum[wid - 1] : 0) + x - v;
    }
    gbar(0, NB1);

    // ---- P4: add region base -> final offsets + cursors ----
    {
        int base = __ldcg(&g_bsum[b]);
        for (int i = r0 + tid; i < r1; i += BT1) {
            int o = g_off[i] + base;
            g_off[i] = o;
            g_cur[i] = o;
        }
        if (gtid == 0) g_off[n] = E;
    }
    gbar(0, NB1);

    // ---- P5: place edges (packed src + weight, one 8B store) ----
    if (is64) {
        for (int e = gtid; e < E; e += NT1) {
            int s = ei[2 * e], d = ei[2 * E + 2 * e];
            int slot = atomicAdd(&g_cur[d], 1);
            int2 p; p.x = s; p.y = __float_as_int(g_dinv[s] * g_dinv[d]);
            g_csr[slot] = p;
        }
    } else {
        for (int e = gtid; e < E; e += NT1) {
            int s = ei[e], d = ei[E + e];
            int slot = atomicAdd(&g_cur[d], 1);
            int2 p; p.x = s; p.y = __float_as_int(g_dinv[s] * g_dinv[d]);
            g_csr[slot] = p;
        }
    }
}

// ==================== GEMM1: h1 = x @ W1 -> fp16 store ====================
__global__ __launch_bounds__(128) void k_gemm1(const float* __restrict__ x,
                                               const float* __restrict__ W,
                                               int n) {
    __shared__ float ws[32][128];
    __shared__ float xs[32][68];
    int tid = threadIdx.x;
    int row0 = blockIdx.x * 64;
    int tr = tid >> 4;
    int tc = tid & 15;
    ull acc[8][4];
#pragma unroll
    for (int r = 0; r < 8; ++r)
#pragma unroll
        for (int j = 0; j < 4; ++j) acc[r][j] = 0ull;

    for (int kc = 0; kc < 4; ++kc) {
        __syncthreads();
        for (int i = tid * 4; i < 32 * 128; i += 128 * 4)
            *(float4*)(&ws[0][0] + i) = *(const float4*)(W + kc * 32 * 128 + i);
        for (int i = tid; i < 64 * 32; i += 128) {
            int r = i >> 5, k = i & 31;
            int gr = row0 + r;
            xs[k][r] = (gr < n) ? x[(size_t)gr * 128 + kc * 32 + k] : 0.0f;
        }
        __syncthreads();
#pragma unroll 4
        for (int k = 0; k < 32; ++k) {
            float4 xa = *(const float4*)&xs[k][tr * 8];
            float4 xb = *(const float4*)&xs[k][tr * 8 + 4];
            float4 wa = *(const float4*)&ws[k][tc * 8];
            float4 wb = *(const float4*)&ws[k][tc * 8 + 4];
            ull wp[4] = { pk2(wa.x, wa.y), pk2(wa.z, wa.w),
                          pk2(wb.x, wb.y), pk2(wb.z, wb.w) };
            ull xd[8] = { pk2(xa.x, xa.x), pk2(xa.y, xa.y),
                          pk2(xa.z, xa.z), pk2(xa.w, xa.w),
                          pk2(xb.x, xb.x), pk2(xb.y, xb.y),
                          pk2(xb.z, xb.z), pk2(xb.w, xb.w) };
#pragma unroll
            for (int r = 0; r < 8; ++r)
#pragma unroll
                for (int j = 0; j < 4; ++j)
                    acc[r][j] = ffma2(xd[r], wp[j], acc[r][j]);
        }
    }
#pragma unroll
    for (int r = 0; r < 8; ++r) {
        int gr = row0 + tr * 8 + r;
        if (gr >= n) continue;
        float2 p0 = up2(acc[r][0]), p1 = up2(acc[r][1]);
        float2 p2 = up2(acc[r][2]), p3 = up2(acc[r][3]);
        __half2 h[4] = { __float22half2_rn(p0), __float22half2_rn(p1),
                         __float22half2_rn(p2), __float22half2_rn(p3) };
        *(uint4*)(g_h1 + (size_t)gr * 128 + tc * 8) = *(const uint4*)h;
    }
}

// ==================== fused gathers ====================
// packed fp16->f32x2 accumulate: acc[j] += f32x2(u.h2[j]) * (w,w)
__device__ __forceinline__ void fma8p(ull* acc, uint4 u, float w) {
    ull ww = pk2(w, w);
    __half2* h = (__half2*)&u;
#pragma unroll
    for (int j = 0; j < 4; ++j) {
        float2 f = __half22float2(h[j]);
        acc[j] = ffma2(pk2(f.x, f.y), ww, acc[j]);
    }
}

__global__ __launch_bounds__(256, 4) void k_gather(float* __restrict__ out,
                                                   const float* __restrict__ b1,
                                                   const float* __restrict__ W2,
                                                   const float* __restrict__ b2,
                                                   int n) {
    __shared__ ull w2p[64 * 16];         // packed pairs: w2p[k2*16+c] = (W2[2k2][c], W2[2k2+1][c])
    __shared__ float rows[8][2][132];    // per warp, per half-warp node row (padded)
    int tid = threadIdx.x;
    for (int i = tid; i < 1024; i += 256) {
        int k2 = i >> 4, c = i & 15;
        w2p[i] = pk2(W2[(2 * k2) * 16 + c], W2[(2 * k2 + 1) * 16 + c]);
    }
    // zero g_deg for the NEXT replay's k_build (stream-ordered; free here)
    for (int i = blockIdx.x * 256 + tid; i < n; i += NB2 * 256) g_deg[i] = 0;
    __syncthreads();

    int warp = tid >> 5, lane = tid & 31;
    int half = lane >> 4, hl = lane & 15;
    int c = hl << 3;                     // 8 halfs (16 B) per lane
    int npair = (n + 1) >> 1;

    // ---- layer 1: half-warp per node (persistent), fused relu + GEMM2 ----
    for (int pair = blockIdx.x * 8 + warp; pair < npair; pair += NB2 * 8) {
        int node = pair * 2 + half;
        if (node < n) {
            ull acc[4];
            float di = g_dinv[node];
            float w0 = di * di;
            {
                uint4 u = *(const uint4*)(g_h1 + (size_t)node * 128 + c);
                ull ww = pk2(w0, w0);
                __half2* h = (__half2*)&u;
#pragma unroll
                for (int j = 0; j < 4; ++j) {
                    float2 f = __half22float2(h[j]);
                    ull t = pk2(f.x, f.y);
                    // acc = t * ww  (mul via fma with 0)
                    acc[j] = ffma2(t, ww, pk2(0.0f, 0.0f));
                }
            }
            int e = g_off[node], e1 = g_off[node + 1];
            if ((e & 1) && e < e1) {     // peel to 16B boundary
                int2 p = g_csr[e];
                uint4 uu = *(const uint4*)(g_h1 + (size_t)p.x * 128 + c);
                fma8p(acc, uu, __int_as_float(p.y));
                ++e;
            }
            const int4* cp = (const int4*)(g_csr + e);   // 16B aligned
            int np = (e1 - e) >> 1;
            int i2 = 0;
            for (; i2 + 2 <= np; i2 += 2) {              // 4 edges per iter
                int4 A = cp[i2], B = cp[i2 + 1];
                uint4 u0 = *(const uint4*)(g_h1 + (size_t)A.x * 128 + c);
                uint4 u1 = *(const uint4*)(g_h1 + (size_t)A.z * 128 + c);
                uint4 u2 = *(const uint4*)(g_h1 + (size_t)B.x * 128 + c);
                uint4 u3 = *(const uint4*)(g_h1 + (size_t)B.z * 128 + c);
                fma8p(acc, u0, __int_as_float(A.y));
                fma8p(acc, u1, __int_as_float(A.w));
                fma8p(acc, u2, __int_as_float(B.y));
                fma8p(acc, u3, __int_as_float(B.w));
            }
            for (; i2 < np; ++i2) {                      // 2 edges
                int4 A = cp[i2];
                uint4 u0 = *(const uint4*)(g_h1 + (size_t)A.x * 128 + c);
                uint4 u1 = *(const uint4*)(g_h1 + (size_t)A.z * 128 + c);
                fma8p(acc, u0, __int_as_float(A.y));
                fma8p(acc, u1, __int_as_float(A.w));
            }
            if ((e1 - e) & 1) {                          // trailing edge
                int2 p = g_csr[e1 - 1];
                uint4 uu = *(const uint4*)(g_h1 + (size_t)p.x * 128 + c);
                fma8p(acc, uu, __int_as_float(p.y));
            }
            float4 ba = *(const float4*)(b1 + c);
            float4 bb = *(const float4*)(b1 + c + 4);
            float2 f0 = up2(acc[0]), f1 = up2(acc[1]);
            float2 f2 = up2(acc[2]), f3 = up2(acc[3]);
            float* rw = &rows[warp][half][c];
            rw[0] = fmaxf(f0.x + ba.x, 0.0f);
            rw[1] = fmaxf(f0.y + ba.y, 0.0f);
            rw[2] = fmaxf(f1.x + ba.z, 0.0f);
            rw[3] = fmaxf(f1.y + ba.w, 0.0f);
            rw[4] = fmaxf(f2.x + bb.x, 0.0f);
            rw[5] = fmaxf(f2.y + bb.y, 0.0f);
            rw[6] = fmaxf(f3.x + bb.z, 0.0f);
            rw[7] = fmaxf(f3.y + bb.w, 0.0f);
        }
        __syncwarp();
        // fused GEMM2: half-warp's 16 lanes produce its node's 16 outputs (packed FFMA2)
        int gnode = pair * 2 + half;
        if (gnode < n) {
            const float* rr = &rows[warp][half][0];
            ull acc = pk2(0.0f, 0.0f);
#pragma unroll 8
            for (int k2 = 0; k2 < 64; k2 += 2) {
                float4 r = *(const float4*)(rr + 2 * k2);   // broadcast LDS.128
                acc = ffma2(pk2(r.x, r.y), w2p[k2 * 16 + hl], acc);
                acc = ffma2(pk2(r.z, r.w), w2p[(k2 + 1) * 16 + hl], acc);
            }
            float2 fa = up2(acc);
            g_h2[(size_t)gnode * 16 + hl] = fa.x + fa.y;
        }
        __syncwarp();
    }

    gbar(1, NB2);

    // ---- layer 2: 4 lanes per node (persistent) + b2 + log_softmax ----
    for (int idx = blockIdx.x * 256 + tid; idx < n * 4; idx += NB2 * 256) {
        int node = idx >> 2;
        int q = (idx & 3) << 2;
        float di = g_dinv[node];
        float w0 = di * di;
        float4 acc = *(const float4*)(g_h2 + (size_t)node * 16 + q);
        acc.x *= w0; acc.y *= w0; acc.z *= w0; acc.w *= w0;
        int e = g_off[node], e1 = g_off[node + 1];
        if ((e & 1) && e < e1) {
            int2 p = g_csr[e];
            float wt = __int_as_float(p.y);
            float4 v = *(const float4*)(g_h2 + (size_t)p.x * 16 + q);
            acc.x += v.x * wt; acc.y += v.y * wt; acc.z += v.z * wt; acc.w += v.w * wt;
            ++e;
        }
        const int4* cp = (const int4*)(g_csr + e);
        int np = (e1 - e) >> 1;
        int i2 = 0;
        for (; i2 + 2 <= np; i2 += 2) {
            int4 A = cp[i2], B = cp[i2 + 1];
            float4 v0 = *(const float4*)(g_h2 + (size_t)A.x * 16 + q);
            float4 v1 = *(const float4*)(g_h2 + (size_t)A.z * 16 + q);
            float4 v2 = *(const float4*)(g_h2 + (size_t)B.x * 16 + q);
            float4 v3 = *(const float4*)(g_h2 + (size_t)B.z * 16 + q);
            float wa = __int_as_float(A.y), wb = __int_as_float(A.w);
            float wc = __int_as_float(B.y), wd = __int_as_float(B.w);
            acc.x += v0.x * wa + v1.x * wb + v2.x * wc + v3.x * wd;
            acc.y += v0.y * wa + v1.y * wb + v2.y * wc + v3.y * wd;
            acc.z += v0.z * wa + v1.z * wb + v2.z * wc + v3.z * wd;
            acc.w += v0.w * wa + v1.w * wb + v2.w * wc + v3.w * wd;
        }
        for (; i2 < np; ++i2) {
            int4 A = cp[i2];
            float4 v0 = *(const float4*)(g_h2 + (size_t)A.x * 16 + q);
            float4 v1 = *(const float4*)(g_h2 + (size_t)A.z * 16 + q);
            float wa = __int_as_float(A.y), wb = __int_as_float(A.w);
            acc.x += v0.x * wa + v1.x * wb;
            acc.y += v0.y * wa + v1.y * wb;
            acc.z += v0.z * wa + v1.z * wb;
            acc.w += v0.w * wa + v1.w * wb;
        }
        if ((e1 - e) & 1) {
            int2 p = g_csr[e1 - 1];
            float wt = __int_as_float(p.y);
            float4 v = *(const float4*)(g_h2 + (size_t)p.x * 16 + q);
            acc.x += v.x * wt; acc.y += v.y * wt; acc.z += v.z * wt; acc.w += v.w * wt;
        }
        float4 b = *(const float4*)(b2 + q);
        float4 v = make_float4(acc.x + b.x, acc.y + b.y, acc.z + b.z, acc.w + b.w);
        float m = fmaxf(fmaxf(v.x, v.y), fmaxf(v.z, v.w));
        m = fmaxf(m, __shfl_xor_sync(0xffffffffu, m, 1, 4));
        m = fmaxf(m, __shfl_xor_sync(0xffffffffu, m, 2, 4));
        float s4 = expf(v.x - m) + expf(v.y - m) + expf(v.z - m) + expf(v.w - m);
        s4 += __shfl_xor_sync(0xffffffffu, s4, 1, 4);
        s4 += __shfl_xor_sync(0xffffffffu, s4, 2, 4);
        float L = m + logf(s4);
        *(float4*)(out + (size_t)node * 16 + q) =
            make_float4(v.x - L, v.y - L, v.z - L, v.w - L);
    }
}

// ---------------- launch: fork/join, fused build || gemm1, then fused gather ----------------
extern "C" void kernel_launch(void* const* d_in, const int* in_sizes, int n_in,
                              void* d_out, int out_size) {
    const float* x  = (const float*)d_in[0];
    const int*   ei = (const int*)d_in[1];
    const float* W1 = (const float*)d_in[2];
    const float* b1 = (const float*)d_in[3];
    const float* W2 = (const float*)d_in[4];
    const float* b2 = (const float*)d_in[5];
    float* out = (float*)d_out;

    int n = in_sizes[0] / 128;
    int E = in_sizes[1] / 2;

    static cudaStream_t s1 = nullptr, s2 = nullptr;
    static cudaEvent_t ev0 = nullptr, ev1 = nullptr, ev2 = nullptr;
    if (!s1) {
        cudaStreamCreateWithFlags(&s1, cudaStreamNonBlocking);
        cudaStreamCreateWithFlags(&s2, cudaStreamNonBlocking);
        cudaEventCreateWithFlags(&ev0, cudaEventDisableTiming);
        cudaEventCreateWithFlags(&ev1, cudaEventDisableTiming);
        cudaEventCreateWithFlags(&ev2, cudaEventDisableTiming);
    }

    cudaEventRecord(ev0, 0);
    cudaStreamWaitEvent(s1, ev0, 0);
    cudaStreamWaitEvent(s2, ev0, 0);

    k_build<<<NB1, BT1, 0, s1>>>(ei, n, E);
    cudaEventRecord(ev1, s1);

    k_gemm1<<<(n + 63) / 64, 128, 0, s2>>>(x, W1, n);
    cudaEventRecord(ev2, s2);

    cudaStreamWaitEvent(0, ev1, 0);
    cudaStreamWaitEvent(0, ev2, 0);

    k_gather<<<NB2, 256>>>(out, b1, W2, b2, n);
}

// round 14
// speedup vs baseline: 1.0179x; 1.0179x over previous
#include <cuda_runtime.h>
#include <cuda_fp16.h>
#include <math.h>

#define NMAX 50000
#define EMAX 800000
#define NB1 148                  // build blocks (1/SM, co-resident)
#define BT1 1024
#define NT1 (NB1 * BT1)
#define NB2 592                  // gather blocks (4/SM via launch_bounds)

typedef unsigned long long ull;

// ---------------- scratch (static device memory) ----------------
__device__ float  g_dinv[NMAX];
__device__ int    g_deg[NMAX];            // zeroed by k_gather (prev replay / static init)
__device__ int    g_off[NMAX + 1];
__device__ int    g_cur[NMAX];
__device__ int    g_bsum[NB1 + 8];
__device__ int    g_csr[EMAX];            // src only (weights factor out)
__device__ __half g_h1[(size_t)NMAX * 128];  // x @ W1 (fp16)
__device__ float  g_h2[(size_t)NMAX * 16];   // (relu(agg1+b1) @ W2) * dinv  (pre-scaled!)

// ---------------- software grid barrier (nanosleep backoff, self-restoring) ----------------
__device__ unsigned g_cnt[2] = {0, 0};
__device__ volatile unsigned g_gen[2] = {0, 0};

__device__ __forceinline__ void gbar(int which, unsigned nb) {
    __syncthreads();
    if (threadIdx.x == 0) {
        __threadfence();
        unsigned g = g_gen[which];
        if (atomicAdd(&g_cnt[which], 1u) == nb - 1u) {
            g_cnt[which] = 0u;
            __threadfence();
            g_gen[which] = g + 1u;
        } else {
            while (g_gen[which] == g) __nanosleep(64);
        }
    }
    __syncthreads();
}

// ---------------- f32x2 packed math helpers ----------------
__device__ __forceinline__ ull pk2(float a, float b) {
    ull r;
    asm("mov.b64 %0, {%1, %2};" : "=l"(r) : "f"(a), "f"(b));
    return r;
}
__device__ __forceinline__ float2 up2(ull v) {
    float2 r;
    asm("mov.b64 {%0, %1}, %2;" : "=f"(r.x), "=f"(r.y) : "l"(v));
    return r;
}
__device__ __forceinline__ ull ffma2(ull a, ull b, ull c) {
    ull d;
    asm("fma.rn.f32x2 %0, %1, %2, %3;" : "=l"(d) : "l"(a), "l"(b), "l"(c));
    return d;
}

// ==================== fused CSR build (4 grid barriers; zeroing done by k_gather) ====================
__global__ __launch_bounds__(BT1) void k_build(const int* __restrict__ ei, int n, int E) {
    __shared__ int wsum[32];
    __shared__ int s_carry;
    int tid = threadIdx.x, lane = tid & 31, wid = tid >> 5;
    int b = blockIdx.x;
    int gtid = b * BT1 + tid;

    // ---- P1: dtype detect (block-local) + in-degree count ----
    // int64 little-endian: odd words = zero high halves; int32: random node ids.
    int is64;
    {
        int v = ei[2 * gtid + 1];                 // gtid < NT1 <= 2E, in-bounds both dtypes
        is64 = __syncthreads_or(v != 0) ? 0 : 1;
    }
    if (is64) {
        for (int e = gtid; e < E; e += NT1) atomicAdd(&g_deg[ei[2 * E + 2 * e]], 1);
    } else {
        for (int e = gtid; e < E; e += NT1) atomicAdd(&g_deg[ei[E + e]], 1);
    }
    gbar(0, NB1);

    // ---- P2: per-block local exclusive scan over contiguous region (+ dinv) ----
    int chunk = (n + NB1 - 1) / NB1;
    int r0 = b * chunk;
    int r1 = min(r0 + chunk, n);
    if (tid == 0) s_carry = 0;
    __syncthreads();
    for (int t0 = r0; t0 < r1; t0 += BT1) {
        int i = t0 + tid;
        int deg = (i < r1) ? __ldcg(&g_deg[i]) : 0;
        int v = deg;
#pragma unroll
        for (int o = 1; o < 32; o <<= 1) {
            int t = __shfl_up_sync(0xffffffffu, v, o);
            if (lane >= o) v += t;
        }
        if (lane == 31) wsum[wid] = v;
        __syncthreads();
        if (wid == 0) {
            int s = wsum[lane];
#pragma unroll
            for (int o = 1; o < 32; o <<= 1) {
                int t = __shfl_up_sync(0xffffffffu, s, o);
                if (lane >= o) s += t;
            }
            wsum[lane] = s;
        }
        __syncthreads();
        int excl = s_carry + (wid ? wsum[wid - 1] : 0) + v - deg;
        if (i < r1) {
            g_off[i] = excl;                       // region-local
            g_dinv[i] = rsqrtf((float)deg + 1.0f);
        }
        __syncthreads();
        if (tid == 0) s_carry += wsum[31];
        __syncthreads();
    }
    if (tid == 0) g_bsum[b] = s_carry;
    gbar(0, NB1);

    // ---- P3: block 0 exclusive-scans the NB1 region totals (parallel) ----
    if (b == 0) {
        int v = (tid < NB1) ? __ldcg(&g_bsum[tid]) : 0;
        int x = v;
#pragma unroll
        for (int o = 1; o < 32; o <<= 1) {
            int t = __shfl_up_sync(0xffffffffu, x, o);
            if (lane >= o) x += t;
        }
        if (lane == 31) wsum[wid] = x;
        __syncthreads();
        if (wid == 0) {
            int s = wsum[lane];
#pragma unroll
            for (int o = 1; o < 32; o <<= 1) {
                int t = __shfl_up_sync(0xffffffffu, s, o);
                if (lane >= o) s += t;
            }
            wsum[lane] = s;
        }
        __syncthreads();
        if (tid < NB1) g_bsum[tid] = (wid ? wsum[wid - 1] : 0) + x - v;
    }
    gbar(0, NB1);

    // ---- P4: add region base -> final offsets + cursors ----
    {
        int base = __ldcg(&g_bsum[b]);
        for (int i = r0 + tid; i < r1; i += BT1) {
            int o = g_off[i] + base;
            g_off[i] = o;
            g_cur[i] = o;
        }
        if (gtid == 0) g_off[n] = E;
    }
    gbar(0, NB1);

    // ---- P5: place edges (src only, one 4B store, no dinv loads) ----
    if (is64) {
        for (int e = gtid; e < E; e += NT1) {
            int s = ei[2 * e], d = ei[2 * E + 2 * e];
            g_csr[atomicAdd(&g_cur[d], 1)] = s;
        }
    } else {
        for (int e = gtid; e < E; e += NT1) {
            int s = ei[e], d = ei[E + e];
            g_csr[atomicAdd(&g_cur[d], 1)] = s;
        }
    }
}

// ==================== GEMM1: h1 = x @ W1 -> fp16 store ====================
__global__ __launch_bounds__(128) void k_gemm1(const float* __restrict__ x,
                                               const float* __restrict__ W,
                                               int n) {
    __shared__ float ws[32][128];
    __shared__ float xs[32][68];
    int tid = threadIdx.x;
    int row0 = blockIdx.x * 64;
    int tr = tid >> 4;
    int tc = tid & 15;
    ull acc[8][4];
#pragma unroll
    for (int r = 0; r < 8; ++r)
#pragma unroll
        for (int j = 0; j < 4; ++j) acc[r][j] = 0ull;

    for (int kc = 0; kc < 4; ++kc) {
        __syncthreads();
        for (int i = tid * 4; i < 32 * 128; i += 128 * 4)
            *(float4*)(&ws[0][0] + i) = *(const float4*)(W + kc * 32 * 128 + i);
        for (int i = tid; i < 64 * 32; i += 128) {
            int r = i >> 5, k = i & 31;
            int gr = row0 + r;
            xs[k][r] = (gr < n) ? x[(size_t)gr * 128 + kc * 32 + k] : 0.0f;
        }
        __syncthreads();
#pragma unroll 4
        for (int k = 0; k < 32; ++k) {
            float4 xa = *(const float4*)&xs[k][tr * 8];
            float4 xb = *(const float4*)&xs[k][tr * 8 + 4];
            float4 wa = *(const float4*)&ws[k][tc * 8];
            float4 wb = *(const float4*)&ws[k][tc * 8 + 4];
            ull wp[4] = { pk2(wa.x, wa.y), pk2(wa.z, wa.w),
                          pk2(wb.x, wb.y), pk2(wb.z, wb.w) };
            ull xd[8] = { pk2(xa.x, xa.x), pk2(xa.y, xa.y),
                          pk2(xa.z, xa.z), pk2(xa.w, xa.w),
                          pk2(xb.x, xb.x), pk2(xb.y, xb.y),
                          pk2(xb.z, xb.z), pk2(xb.w, xb.w) };
#pragma unroll
            for (int r = 0; r < 8; ++r)
#pragma unroll
                for (int j = 0; j < 4; ++j)
                    acc[r][j] = ffma2(xd[r], wp[j], acc[r][j]);
        }
    }
#pragma unroll
    for (int r = 0; r < 8; ++r) {
        int gr = row0 + tr * 8 + r;
        if (gr >= n) continue;
        float2 p0 = up2(acc[r][0]), p1 = up2(acc[r][1]);
        float2 p2 = up2(acc[r][2]), p3 = up2(acc[r][3]);
        __half2 h[4] = { __float22half2_rn(p0), __float22half2_rn(p1),
                         __float22half2_rn(p2), __float22half2_rn(p3) };
        *(uint4*)(g_h1 + (size_t)gr * 128 + tc * 8) = *(const uint4*)h;
    }
}

// ==================== fused gathers ====================
// packed fp16->f32x2 accumulate: acc[j] += f32x2(u.h2[j]) * (w,w)
__device__ __forceinline__ void fma8p(ull* acc, uint4 u, float w) {
    ull ww = pk2(w, w);
    __half2* h = (__half2*)&u;
#pragma unroll
    for (int j = 0; j < 4; ++j) {
        float2 f = __half22float2(h[j]);
        acc[j] = ffma2(pk2(f.x, f.y), ww, acc[j]);
    }
}

__global__ __launch_bounds__(256, 4) void k_gather(float* __restrict__ out,
                                                   const float* __restrict__ b1,
                                                   const float* __restrict__ W2,
                                                   const float* __restrict__ b2,
                                                   int n) {
    __shared__ float w2s[128 * 16];      // row-major [k][c]
    __shared__ float rows[8][2][132];    // per warp, per half-warp node row (padded)
    int tid = threadIdx.x;
    for (int i = tid; i < 2048; i += 256) w2s[i] = W2[i];
    // zero g_deg for the NEXT replay's k_build (stream-ordered; free here)
    for (int i = blockIdx.x * 256 + tid; i < n; i += NB2 * 256) g_deg[i] = 0;
    __syncthreads();

    int warp = tid >> 5, lane = tid & 31;
    int half = lane >> 4, hl = lane & 15;
    int c = hl << 3;                     // 8 halfs (16 B) per lane
    int npair = (n + 1) >> 1;

    // ---- layer 1: half-warp per node (persistent), fused relu + GEMM2 ----
    // agg1 = dinv[d] * ( h1[d]*dinv[d] + sum_s h1[s]*dinv[s] )
    for (int pair = blockIdx.x * 8 + warp; pair < npair; pair += NB2 * 8) {
        int node = pair * 2 + half;
        float di = 0.0f;
        if (node < n) {
            di = g_dinv[node];
            ull acc[4] = {0ull, 0ull, 0ull, 0ull};
            {
                uint4 u = *(const uint4*)(g_h1 + (size_t)node * 128 + c);
                fma8p(acc, u, di);                       // self term: weight dinv[node]
            }
            int e = g_off[node], e1 = g_off[node + 1];
            for (; e + 4 <= e1; e += 4) {
                int s0 = g_csr[e],     s1 = g_csr[e + 1];
                int s2 = g_csr[e + 2], s3 = g_csr[e + 3];
                float w0 = g_dinv[s0], w1 = g_dinv[s1];
                float w2 = g_dinv[s2], w3 = g_dinv[s3];
                uint4 u0 = *(const uint4*)(g_h1 + (size_t)s0 * 128 + c);
                uint4 u1 = *(const uint4*)(g_h1 + (size_t)s1 * 128 + c);
                uint4 u2 = *(const uint4*)(g_h1 + (size_t)s2 * 128 + c);
                uint4 u3 = *(const uint4*)(g_h1 + (size_t)s3 * 128 + c);
                fma8p(acc, u0, w0);
                fma8p(acc, u1, w1);
                fma8p(acc, u2, w2);
                fma8p(acc, u3, w3);
            }
            for (; e < e1; ++e) {
                int s = g_csr[e];
                uint4 u = *(const uint4*)(g_h1 + (size_t)s * 128 + c);
                fma8p(acc, u, g_dinv[s]);
            }
            float4 ba = *(const float4*)(b1 + c);
            float4 bb = *(const float4*)(b1 + c + 4);
            float2 f0 = up2(acc[0]), f1 = up2(acc[1]);
            float2 f2 = up2(acc[2]), f3 = up2(acc[3]);
            float* rw = &rows[warp][half][c];
            rw[0] = fmaxf(f0.x * di + ba.x, 0.0f);
            rw[1] = fmaxf(f0.y * di + ba.y, 0.0f);
            rw[2] = fmaxf(f1.x * di + ba.z, 0.0f);
            rw[3] = fmaxf(f1.y * di + ba.w, 0.0f);
            rw[4] = fmaxf(f2.x * di + bb.x, 0.0f);
            rw[5] = fmaxf(f2.y * di + bb.y, 0.0f);
            rw[6] = fmaxf(f3.x * di + bb.z, 0.0f);
            rw[7] = fmaxf(f3.y * di + bb.w, 0.0f);
        }
        __syncwarp();
        // fused GEMM2 -> store h2' = h2 * dinv[node]  (pre-scaled for weight-free layer 2)
        if (node < n) {
            const float* rr = &rows[warp][half][0];
            float s = 0.0f;
#pragma unroll 8
            for (int k = 0; k < 128; k += 4) {
                float4 r = *(const float4*)(rr + k);
                s += r.x * w2s[(k + 0) * 16 + hl];
                s += r.y * w2s[(k + 1) * 16 + hl];
                s += r.z * w2s[(k + 2) * 16 + hl];
                s += r.w * w2s[(k + 3) * 16 + hl];
            }
            g_h2[(size_t)node * 16 + hl] = s * di;
        }
        __syncwarp();
    }

    gbar(1, NB2);

    // ---- layer 2: weight-free row sum (4 lanes/node) + b2 + log_softmax ----
    // out = dinv[d] * ( h2'[d] + sum_s h2'[s] ) + b2
    for (int idx = blockIdx.x * 256 + tid; idx < n * 4; idx += NB2 * 256) {
        int node = idx >> 2;
        int q = (idx & 3) << 2;
        float di = g_dinv[node];
        float4 acc = *(const float4*)(g_h2 + (size_t)node * 16 + q);   // self term h2'[d]
        int e = g_off[node], e1 = g_off[node + 1];
        for (; e + 4 <= e1; e += 4) {
            int s0 = g_csr[e],     s1 = g_csr[e + 1];
            int s2 = g_csr[e + 2], s3 = g_csr[e + 3];
            float4 v0 = *(const float4*)(g_h2 + (size_t)s0 * 16 + q);
            float4 v1 = *(const float4*)(g_h2 + (size_t)s1 * 16 + q);
            float4 v2 = *(const float4*)(g_h2 + (size_t)s2 * 16 + q);
            float4 v3 = *(const float4*)(g_h2 + (size_t)s3 * 16 + q);
            acc.x += v0.x + v1.x + v2.x + v3.x;
            acc.y += v0.y + v1.y + v2.y + v3.y;
            acc.z += v0.z + v1.z + v2.z + v3.z;
            acc.w += v0.w + v1.w + v2.w + v3.w;
        }
        for (; e < e1; ++e) {
            int s = g_csr[e];
            float4 v = *(const float4*)(g_h2 + (size_t)s * 16 + q);
            acc.x += v.x; acc.y += v.y; acc.z += v.z; acc.w += v.w;
        }
        float4 b = *(const float4*)(b2 + q);
        float4 v = make_float4(acc.x * di + b.x, acc.y * di + b.y,
                               acc.z * di + b.z, acc.w * di + b.w);
        float m = fmaxf(fmaxf(v.x, v.y), fmaxf(v.z, v.w));
        m = fmaxf(m, __shfl_xor_sync(0xffffffffu, m, 1, 4));
        m = fmaxf(m, __shfl_xor_sync(0xffffffffu, m, 2, 4));
        float s4 = expf(v.x - m) + expf(v.y - m) + expf(v.z - m) + expf(v.w - m);
        s4 += __shfl_xor_sync(0xffffffffu, s4, 1, 4);
        s4 += __shfl_xor_sync(0xffffffffu, s4, 2, 4);
        float L = m + logf(s4);
        *(float4*)(out + (size_t)node * 16 + q) =
            make_float4(v.x - L, v.y - L, v.z - L, v.w - L);
    }
}

// ---------------- launch: fork/join, fused build || gemm1, then fused gather ----------------
extern "C" void kernel_launch(void* const* d_in, const int* in_sizes, int n_in,
                              void* d_out, int out_size) {
    const float* x  = (const float*)d_in[0];
    const int*   ei = (const int*)d_in[1];
    const float* W1 = (const float*)d_in[2];
    const float* b1 = (const float*)d_in[3];
    const float* W2 = (const float*)d_in[4];
    const float* b2 = (const float*)d_in[5];
    float* out = (float*)d_out;

    int n = in_sizes[0] / 128;
    int E = in_sizes[1] / 2;

    static cudaStream_t s1 = nullptr, s2 = nullptr;
    static cudaEvent_t ev0 = nullptr, ev1 = nullptr, ev2 = nullptr;
    if (!s1) {
        cudaStreamCreateWithFlags(&s1, cudaStreamNonBlocking);
        cudaStreamCreateWithFlags(&s2, cudaStreamNonBlocking);
        cudaEventCreateWithFlags(&ev0, cudaEventDisableTiming);
        cudaEventCreateWithFlags(&ev1, cudaEventDisableTiming);
        cudaEventCreateWithFlags(&ev2, cudaEventDisableTiming);
    }

    cudaEventRecord(ev0, 0);
    cudaStreamWaitEvent(s1, ev0, 0);
    cudaStreamWaitEvent(s2, ev0, 0);

    k_build<<<NB1, BT1, 0, s1>>>(ei, n, E);
    cudaEventRecord(ev1, s1);

    k_gemm1<<<(n + 63) / 64, 128, 0, s2>>>(x, W1, n);
    cudaEventRecord(ev2, s2);

    cudaStreamWaitEvent(0, ev1, 0);
    cudaStreamWaitEvent(0, ev2, 0);

    k_gather<<<NB2, 256>>>(out, b1, W2, b2, n);
}